// round 9
// baseline (speedup 1.0000x reference)
#include <cuda_runtime.h>
#include <cuda_fp16.h>
#include <cstdint>
#include <math.h>

#define NMAX 50176
#define EMAX 1700000
#define NEG 0.2f
#define FULL 0xffffffffu

// ---------------- device scratch (static; no allocation) ----------------
__device__ __half g_h1h[(size_t)NMAX * 48];   // 96B rows, 16B-aligned lanes
__device__ __half g_h2h[(size_t)NMAX * 64];   // padded to 128B rows
__device__ float g_out1[(size_t)NMAX * 48];
__device__ float2 g_p3[NMAX];   // (as3*d, d) packed for layer-3 gather
__device__ float g_as[NMAX];    // alphas of current layer (1 then 2)
__device__ float g_ad[NMAX];
__device__ float g_adB[NMAX];   // layer-3 ad
__device__ int   g_cnt[NMAX + 1];
__device__ int   g_ro[NMAX + 1];
__device__ int   g_nxt[NMAX];
__device__ int   g_csrc[EMAX];
__device__ int   g_bsum[64];
__device__ int   g_boff[64];
__device__ int   g_is64;
__device__ unsigned g_mx1, g_mx2, g_mx3;  // encoded global max of as per layer

__device__ __forceinline__ float lrelu(float x) { return x > 0.f ? x : NEG * x; }

// monotone float <-> uint encoding for atomicMax over signed floats
__device__ __forceinline__ unsigned fenc(float f) {
    unsigned u = __float_as_uint(f);
    return (u & 0x80000000u) ? ~u : (u | 0x80000000u);
}
__device__ __forceinline__ float fdec(unsigned u) {
    return (u & 0x80000000u) ? __uint_as_float(u & 0x7fffffffu) : __uint_as_float(~u);
}

__global__ void init_k() { g_mx1 = 0u; g_mx2 = 0u; g_mx3 = 0u; }

// ---------------- edge-index dtype detection ----------------
__global__ void detect_k(const void* ei) {
    int lane = threadIdx.x;
    const int* p = (const int*)ei;
    int v = p[2 * lane + 1];
    unsigned b = __ballot_sync(FULL, v == 0);
    if (lane == 0) g_is64 = (b == FULL) ? 1 : 0;
}

__device__ __forceinline__ int edge_val(const void* ei, int idx) {
    if (g_is64) return (int)((const long long*)ei)[idx];
    return ((const int*)ei)[idx];
}

// ---------------- CSR build ----------------
__global__ void zero_k(int n) {
    int i = blockIdx.x * blockDim.x + threadIdx.x;
    if (i < n) g_cnt[i] = 0;
}

// 4 edges/thread for MLP
__global__ void hist_k(const void* ei, int E) {
    int base = (blockIdx.x * blockDim.x + threadIdx.x) * 4;
    int d[4];
    #pragma unroll
    for (int k = 0; k < 4; k++)
        d[k] = (base + k < E) ? edge_val(ei, E + base + k) : -1;
    #pragma unroll
    for (int k = 0; k < 4; k++)
        if (d[k] >= 0) atomicAdd(&g_cnt[d[k]], 1);
}

// multi-block exclusive scan of g_cnt[0..N) -> g_ro ; 1024 elems/block
__global__ __launch_bounds__(256) void scanA_k(int N) {
    __shared__ int wsum[8];
    int tid = threadIdx.x, lane = tid & 31, wid = tid >> 5;
    int base = blockIdx.x * 1024 + tid * 4;
    int v[4];
    #pragma unroll
    for (int k = 0; k < 4; k++) v[k] = (base + k < N) ? g_cnt[base + k] : 0;
    int s4 = v[0] + v[1] + v[2] + v[3];
    int x = s4;
    #pragma unroll
    for (int o = 1; o < 32; o <<= 1) {
        int t = __shfl_up_sync(FULL, x, o);
        if (lane >= o) x += t;
    }
    if (lane == 31) wsum[wid] = x;
    __syncthreads();
    if (wid == 0 && lane < 8) {
        int w = wsum[lane];
        #pragma unroll
        for (int o = 1; o < 8; o <<= 1) {
            int t = __shfl_up_sync(0xffu, w, o);
            if (lane >= o) w += t;
        }
        wsum[lane] = w;
    }
    __syncthreads();
    int excl = (wid ? wsum[wid - 1] : 0) + x - s4;
    int run = excl;
    #pragma unroll
    for (int k = 0; k < 4; k++) {
        if (base + k < N) g_ro[base + k] = run;
        run += v[k];
    }
    if (tid == 255) g_bsum[blockIdx.x] = wsum[7];
}

__global__ void scanB_k(int nb, int N) {
    int tid = threadIdx.x;  // 64 threads
    int lane = tid & 31, wid = tid >> 5;
    __shared__ int w0tot;
    int v = (tid < nb) ? g_bsum[tid] : 0;
    int x = v;
    #pragma unroll
    for (int o = 1; o < 32; o <<= 1) {
        int t = __shfl_up_sync(FULL, x, o);
        if (lane >= o) x += t;
    }
    if (wid == 0 && lane == 31) w0tot = x;
    __syncthreads();
    if (wid == 1) x += w0tot;
    g_boff[tid] = x - v;
    if (tid == 63) g_ro[N] = x;
}

__global__ __launch_bounds__(256) void scanC_k(int N) {
    int base = blockIdx.x * 1024 + threadIdx.x * 4;
    int off = g_boff[blockIdx.x];
    #pragma unroll
    for (int k = 0; k < 4; k++) {
        int i = base + k;
        if (i < N) {
            int r = g_ro[i] + off;
            g_ro[i] = r;
            g_nxt[i] = r;
        }
    }
}

// 4 edges/thread for MLP
__global__ void scat_k(const void* ei, int E) {
    int base = (blockIdx.x * blockDim.x + threadIdx.x) * 4;
    int s[4], d[4];
    #pragma unroll
    for (int k = 0; k < 4; k++) {
        int e = base + k;
        if (e < E) { s[k] = edge_val(ei, e); d[k] = edge_val(ei, E + e); }
        else d[k] = -1;
    }
    #pragma unroll
    for (int k = 0; k < 4; k++) {
        if (d[k] >= 0) {
            int p = atomicAdd(&g_nxt[d[k]], 1);
            g_csrc[p] = s[k];
        }
    }
}

// ---------------- GEMM layer 1: [N,256] x [256,48] -> g_h1h ; fused alpha + maxAS ----------------
__global__ __launch_bounds__(256) void gemm1_k(const float* __restrict__ X,
                                               const float* __restrict__ W,
                                               const float* __restrict__ av_s,
                                               const float* __restrict__ av_d, int N) {
    __shared__ float sX[64][68];
    __shared__ float sW[64][48];
    __shared__ float sWm[8];
    int tid = threadIdx.x;
    int tx = tid & 15, ty = tid >> 4;
    int lane = tid & 31, wid = tid >> 5;
    int row0 = blockIdx.x * 64;
    float acc[4][3];
    #pragma unroll
    for (int i = 0; i < 4; i++)
        #pragma unroll
        for (int j = 0; j < 3; j++) acc[i][j] = 0.f;

    for (int k0 = 0; k0 < 256; k0 += 64) {
        for (int i = tid; i < 64 * 16; i += 256) {
            int r = i >> 4; int kq = (i & 15) * 4;
            int gr = row0 + r;
            float4 v = (gr < N) ? *(const float4*)&X[(size_t)gr * 256 + k0 + kq]
                                : make_float4(0.f, 0.f, 0.f, 0.f);
            *(float4*)&sX[r][kq] = v;
        }
        for (int i = tid; i < 64 * 12; i += 256) {
            int r = i / 12; int cq = (i % 12) * 4;
            float4 v = *(const float4*)&W[(size_t)(k0 + r) * 48 + cq];
            *(float4*)&sW[r][cq] = v;
        }
        __syncthreads();
        #pragma unroll 16
        for (int k = 0; k < 64; k++) {
            float a0 = sX[ty * 4 + 0][k], a1 = sX[ty * 4 + 1][k];
            float a2 = sX[ty * 4 + 2][k], a3 = sX[ty * 4 + 3][k];
            float w0 = sW[k][tx * 3 + 0], w1 = sW[k][tx * 3 + 1], w2 = sW[k][tx * 3 + 2];
            acc[0][0] += a0 * w0; acc[0][1] += a0 * w1; acc[0][2] += a0 * w2;
            acc[1][0] += a1 * w0; acc[1][1] += a1 * w1; acc[1][2] += a1 * w2;
            acc[2][0] += a2 * w0; acc[2][1] += a2 * w1; acc[2][2] += a2 * w2;
            acc[3][0] += a3 * w0; acc[3][1] += a3 * w1; acc[3][2] += a3 * w2;
        }
        __syncthreads();
    }
    #pragma unroll
    for (int i = 0; i < 4; i++) {
        int gr = row0 + ty * 4 + i;
        if (gr < N) {
            #pragma unroll
            for (int j = 0; j < 3; j++)
                g_h1h[(size_t)gr * 48 + tx * 3 + j] = __float2half(acc[i][j]);
        }
    }
    // fused alpha: reduce over 16 threads of the same row group
    float a_s[3], a_d[3];
    #pragma unroll
    for (int j = 0; j < 3; j++) { a_s[j] = av_s[tx * 3 + j]; a_d[j] = av_d[tx * 3 + j]; }
    float pmax = -INFINITY;
    #pragma unroll
    for (int i = 0; i < 4; i++) {
        float ps = acc[i][0] * a_s[0] + acc[i][1] * a_s[1] + acc[i][2] * a_s[2];
        float pd = acc[i][0] * a_d[0] + acc[i][1] * a_d[1] + acc[i][2] * a_d[2];
        #pragma unroll
        for (int o = 8; o; o >>= 1) {
            ps += __shfl_down_sync(FULL, ps, o, 16);
            pd += __shfl_down_sync(FULL, pd, o, 16);
        }
        if (tx == 0) {
            int gr = row0 + ty * 4 + i;
            if (gr < N) { g_as[gr] = ps; g_ad[gr] = pd; pmax = fmaxf(pmax, ps); }
        }
    }
    pmax = fmaxf(pmax, __shfl_xor_sync(FULL, pmax, 16));
    if (lane == 0) sWm[wid] = pmax;
    __syncthreads();
    if (wid == 0) {
        float v = (lane < 8) ? sWm[lane] : -INFINITY;
        #pragma unroll
        for (int o = 4; o; o >>= 1) v = fmaxf(v, __shfl_down_sync(FULL, v, o));
        if (lane == 0) atomicMax(&g_mx1, fenc(v));
    }
}

// ---------------- GEMM layer 2: g_out1 [N,48] x [48,60] -> g_h2h (padded 64) ----------------
__global__ __launch_bounds__(256) void gemm2_k(const float* __restrict__ W,
                                               const float* __restrict__ av_s,
                                               const float* __restrict__ av_d, int N) {
    __shared__ float sX[64][52];
    __shared__ float sW[48][64];
    __shared__ float sWm[8];
    int tid = threadIdx.x;
    int tx = tid & 15, ty = tid >> 4;
    int lane = tid & 31, wid = tid >> 5;
    int row0 = blockIdx.x * 64;

    for (int i = tid; i < 768; i += 256) {
        int r = i / 12; int kq = (i % 12) * 4;
        int gr = row0 + r;
        float4 v = (gr < N) ? *(const float4*)&g_out1[(size_t)gr * 48 + kq]
                            : make_float4(0.f, 0.f, 0.f, 0.f);
        *(float4*)&sX[r][kq] = v;
    }
    for (int i = tid; i < 720; i += 256) {
        int r = i / 15; int cq = (i % 15) * 4;
        float4 v = *(const float4*)&W[(size_t)r * 60 + cq];
        *(float4*)&sW[r][cq] = v;
    }
    __syncthreads();

    float acc[4][4];
    #pragma unroll
    for (int i = 0; i < 4; i++)
        #pragma unroll
        for (int j = 0; j < 4; j++) acc[i][j] = 0.f;

    #pragma unroll 12
    for (int k = 0; k < 48; k++) {
        float a0 = sX[ty * 4 + 0][k], a1 = sX[ty * 4 + 1][k];
        float a2 = sX[ty * 4 + 2][k], a3 = sX[ty * 4 + 3][k];
        float4 w = *(const float4*)&sW[k][tx * 4];
        acc[0][0] += a0 * w.x; acc[0][1] += a0 * w.y; acc[0][2] += a0 * w.z; acc[0][3] += a0 * w.w;
        acc[1][0] += a1 * w.x; acc[1][1] += a1 * w.y; acc[1][2] += a1 * w.z; acc[1][3] += a1 * w.w;
        acc[2][0] += a2 * w.x; acc[2][1] += a2 * w.y; acc[2][2] += a2 * w.z; acc[2][3] += a2 * w.w;
        acc[3][0] += a3 * w.x; acc[3][1] += a3 * w.y; acc[3][2] += a3 * w.z; acc[3][3] += a3 * w.w;
    }
    #pragma unroll
    for (int i = 0; i < 4; i++) {
        int gr = row0 + ty * 4 + i;
        if (gr < N) {
            int c0 = tx * 4;
            float v0 = (c0 + 0 < 60) ? acc[i][0] : 0.f;
            float v1 = (c0 + 1 < 60) ? acc[i][1] : 0.f;
            float v2 = (c0 + 2 < 60) ? acc[i][2] : 0.f;
            float v3 = (c0 + 3 < 60) ? acc[i][3] : 0.f;
            __half2 p01 = __floats2half2_rn(v0, v1);
            __half2 p23 = __floats2half2_rn(v2, v3);
            uint2 pk = make_uint2(*(unsigned*)&p01, *(unsigned*)&p23);
            *(uint2*)&g_h2h[(size_t)gr * 64 + c0] = pk;
        }
    }
    // fused alpha (cols >= 60 masked out)
    float a_s[4], a_d[4];
    #pragma unroll
    for (int j = 0; j < 4; j++) {
        int c = tx * 4 + j;
        a_s[j] = (c < 60) ? av_s[c] : 0.f;
        a_d[j] = (c < 60) ? av_d[c] : 0.f;
    }
    float pmax = -INFINITY;
    #pragma unroll
    for (int i = 0; i < 4; i++) {
        float ps = acc[i][0] * a_s[0] + acc[i][1] * a_s[1] + acc[i][2] * a_s[2] + acc[i][3] * a_s[3];
        float pd = acc[i][0] * a_d[0] + acc[i][1] * a_d[1] + acc[i][2] * a_d[2] + acc[i][3] * a_d[3];
        #pragma unroll
        for (int o = 8; o; o >>= 1) {
            ps += __shfl_down_sync(FULL, ps, o, 16);
            pd += __shfl_down_sync(FULL, pd, o, 16);
        }
        if (tx == 0) {
            int gr = row0 + ty * 4 + i;
            if (gr < N) { g_as[gr] = ps; g_ad[gr] = pd; pmax = fmaxf(pmax, ps); }
        }
    }
    pmax = fmaxf(pmax, __shfl_xor_sync(FULL, pmax, 16));
    if (lane == 0) sWm[wid] = pmax;
    __syncthreads();
    if (wid == 0) {
        float v = (lane < 8) ? sWm[lane] : -INFINITY;
        #pragma unroll
        for (int o = 4; o; o >>= 1) v = fmaxf(v, __shfl_down_sync(FULL, v, o));
        if (lane == 0) atomicMax(&g_mx2, fenc(v));
    }
}

// ---------------- fused segment softmax + aggregation (warp per node, single pass) ----------------
// Gathers are fp16 (payload only); logits/softmax/accumulation stay fp32.
// LAYER==1: reads g_h1h (stride 48); writes g_out1.
// LAYER==2: reads g_h2h (stride 64, cols 60..63 zero); epilogue computes
//           h3 = out2 @ W3, packs (as3*h3, h3) into g_p3, writes g_adB, max->g_mx3.
template <int LAYER>
__global__ __launch_bounds__(256) void agg_k(const float* __restrict__ bias,
                                             const float* __restrict__ W3,
                                             const float* __restrict__ as3,
                                             const float* __restrict__ ad3, int N) {
    constexpr int ST = (LAYER == 1) ? 48 : 64;   // row stride in halfs
    constexpr int LN = ST / 8;                   // active gather lanes (6 or 8)
    const __half* h = (LAYER == 1) ? g_h1h : g_h2h;
    __shared__ float sWm[8];

    int tid = threadIdx.x;
    int n = (blockIdx.x * blockDim.x + tid) >> 5;
    int lane = tid & 31, wid = tid >> 5;
    bool valid = n < N;

    float maxAS = fdec((LAYER == 1) ? g_mx1 : g_mx2);
    int beg = 0, end = 0;
    float adn = 0.f, lself = 0.f, m = 0.f;
    if (valid) {
        beg = g_ro[n]; end = g_ro[n + 1];
        adn = g_ad[n];
        lself = lrelu(g_as[n] + adn);
        m = lrelu(maxAS + adn);
    }

    int half_id = lane >> 4;
    int hl = lane & 15;
    const bool act = hl < LN;
    float acc[8];
    #pragma unroll
    for (int k = 0; k < 8; k++) acc[k] = 0.f;
    float Sp = 0.f;

    for (int j0 = beg; j0 < end; j0 += 32) {
        int j = j0 + lane;
        int s = 0; float e = 0.f;
        if (j < end) {
            s = g_csrc[j];
            e = __expf(lrelu(g_as[s] + adn) - m);
            Sp += e;
        }
        int cnt = min(32, end - j0);
        for (int jj = 0; jj < cnt; jj += 2) {
            int idx = jj + half_id;
            float ee = __shfl_sync(FULL, e, idx);
            int ss = __shfl_sync(FULL, s, idx);
            if (act && idx < cnt) {
                float4 raw = *(const float4*)(h + (size_t)ss * ST + hl * 8);
                const __half2* hp = (const __half2*)&raw;
                #pragma unroll
                for (int q = 0; q < 4; q++) {
                    float2 f = __half22float2(hp[q]);
                    acc[2 * q + 0] += ee * f.x;
                    acc[2 * q + 1] += ee * f.y;
                }
            }
        }
    }
    // combine halves: lane L += lane L+16
    #pragma unroll
    for (int k = 0; k < 8; k++) acc[k] += __shfl_down_sync(FULL, acc[k], 16);

    float es = __expf(lself - m);
    if (valid && lane < LN) {
        float4 raw = *(const float4*)(h + (size_t)n * ST + lane * 8);
        const __half2* hp = (const __half2*)&raw;
        #pragma unroll
        for (int q = 0; q < 4; q++) {
            float2 f = __half22float2(hp[q]);
            acc[2 * q + 0] += es * f.x;
            acc[2 * q + 1] += es * f.y;
        }
    }
    if (lane == 0) Sp += es;
    #pragma unroll
    for (int o = 16; o; o >>= 1) Sp += __shfl_xor_sync(FULL, Sp, o);

    float inv = 1.f / (Sp + 1e-16f);
    float o8[8];
    if (lane < LN) {
        #pragma unroll
        for (int k = 0; k < 8; k++) {
            int c = lane * 8 + k;
            float b = (LAYER == 2 && c >= 60) ? 0.f : bias[c];
            o8[k] = fmaxf(acc[k] * inv + b, 0.f);
        }
        if (LAYER == 1 && valid) {
            float* orow = g_out1 + (size_t)n * 48 + lane * 8;
            *(float4*)orow = make_float4(o8[0], o8[1], o8[2], o8[3]);
            *(float4*)(orow + 4) = make_float4(o8[4], o8[5], o8[6], o8[7]);
        }
    }
    if (LAYER == 2) {
        // fused layer-3 projection + alphas + maxAS3
        float d = 0.f;
        if (lane < LN) {
            #pragma unroll
            for (int k = 0; k < 8; k++) {
                int c = lane * 8 + k;
                if (c < 60) d += o8[k] * W3[c];
            }
        }
        #pragma unroll
        for (int o = 16; o; o >>= 1) d += __shfl_xor_sync(FULL, d, o);
        float pm = -INFINITY;
        if (valid && lane == 0) {
            float a = d * as3[0];
            g_p3[n] = make_float2(a, d);
            g_adB[n] = d * ad3[0];
            pm = a;
        }
        if (lane == 0) sWm[wid] = pm;
        __syncthreads();
        if (wid == 0) {
            float v = (lane < 8) ? sWm[lane] : -INFINITY;
            #pragma unroll
            for (int o = 4; o; o >>= 1) v = fmaxf(v, __shfl_down_sync(FULL, v, o));
            if (lane == 0) atomicMax(&g_mx3, fenc(v));
        }
    }
}

// ---------------- layer 3 aggregation (scalar feature, single pass) ----------------
__global__ __launch_bounds__(256) void agg3_k(const float* __restrict__ b3,
                                              float* __restrict__ out, int N) {
    int n = (blockIdx.x * blockDim.x + threadIdx.x) >> 5;
    int lane = threadIdx.x & 31;
    if (n >= N) return;
    int beg = g_ro[n], end = g_ro[n + 1];
    float adn = g_adB[n];
    float2 pn = g_p3[n];
    float lself = lrelu(pn.x + adn);
    float m = lrelu(fdec(g_mx3) + adn);
    float S = 0.f, A = 0.f;
    for (int j = beg + lane; j < end; j += 32) {
        int s = g_csrc[j];
        float2 p = g_p3[s];
        float e = __expf(lrelu(p.x + adn) - m);
        S += e;
        A += e * p.y;
    }
    if (lane == 0) {
        float es = __expf(lself - m);
        S += es;
        A += es * pn.y;
    }
    #pragma unroll
    for (int o = 16; o; o >>= 1) {
        S += __shfl_xor_sync(FULL, S, o);
        A += __shfl_xor_sync(FULL, A, o);
    }
    if (lane == 0) out[n] = A / (S + 1e-16f) + b3[0];
}

// ---------------- launch ----------------
extern "C" void kernel_launch(void* const* d_in, const int* in_sizes, int n_in,
                              void* d_out, int out_size) {
    const float* x   = (const float*)d_in[0];
    const void*  ei  = d_in[1];
    // d_in[2] = edge_attr (ignored by the reference model)
    const float* W1  = (const float*)d_in[3];
    const float* as1 = (const float*)d_in[4];
    const float* ad1 = (const float*)d_in[5];
    const float* b1  = (const float*)d_in[6];
    const float* W2  = (const float*)d_in[7];
    const float* as2 = (const float*)d_in[8];
    const float* ad2 = (const float*)d_in[9];
    const float* b2  = (const float*)d_in[10];
    const float* W3  = (const float*)d_in[11];
    const float* as3 = (const float*)d_in[12];
    const float* ad3 = (const float*)d_in[13];
    const float* b3  = (const float*)d_in[14];

    int N = out_size;            // output is [N] floats
    int E = in_sizes[1] / 2;     // edge_index is [2, E]

    int blocksE4 = (E + 1023) / 1024;  // 4 edges/thread
    int wb = (N + 7) / 8;        // warp-per-node, 8 warps/block
    int gb = (N + 63) / 64;      // gemm row tiles
    int nb = (N + 1023) / 1024;  // scan blocks

    // one-time side-stream infrastructure (created on first, uncaptured, call)
    static cudaStream_t s2 = nullptr;
    static cudaEvent_t evFork = nullptr, evJoin = nullptr;
    if (s2 == nullptr) {
        cudaStreamCreateWithFlags(&s2, cudaStreamNonBlocking);
        cudaEventCreateWithFlags(&evFork, cudaEventDisableTiming);
        cudaEventCreateWithFlags(&evJoin, cudaEventDisableTiming);
    }

    init_k<<<1, 1>>>();

    // fork: CSR build on s2, GEMM1 on the main (captured) stream
    cudaEventRecord(evFork, 0);
    cudaStreamWaitEvent(s2, evFork, 0);

    zero_k<<<(N + 1023) / 1024, 1024, 0, s2>>>(N);
    detect_k<<<1, 32, 0, s2>>>(ei);
    hist_k<<<blocksE4, 256, 0, s2>>>(ei, E);
    scanA_k<<<nb, 256, 0, s2>>>(N);
    scanB_k<<<1, 64, 0, s2>>>(nb, N);
    scanC_k<<<nb, 256, 0, s2>>>(N);
    scat_k<<<blocksE4, 256, 0, s2>>>(ei, E);
    cudaEventRecord(evJoin, s2);

    gemm1_k<<<gb, 256>>>(x, W1, as1, ad1, N);

    // join: everything after needs both CSR and h1/alpha1
    cudaStreamWaitEvent(0, evJoin, 0);

    agg_k<1><<<wb, 256>>>(b1, nullptr, nullptr, nullptr, N);
    gemm2_k<<<gb, 256>>>(W2, as2, ad2, N);
    agg_k<2><<<wb, 256>>>(b2, W3, as3, ad3, N);
    agg3_k<<<wb, 256>>>(b3, (float*)d_out, N);
}

// round 10
// speedup vs baseline: 1.0665x; 1.0665x over previous
#include <cuda_runtime.h>
#include <cuda_fp16.h>
#include <cstdint>
#include <math.h>

#define NMAX 50176
#define EMAX 1700000
#define NEG 0.2f
#define FULL 0xffffffffu

// ---------------- device scratch (static; no allocation) ----------------
__device__ float g_h1[(size_t)NMAX * 48];
__device__ float g_out1[(size_t)NMAX * 48];
__device__ __half g_h2h[(size_t)NMAX * 64];  // fp16, padded to 128B rows
__device__ float2 g_p3[NMAX];   // (as3*d, d) packed for layer-3 gather
__device__ float g_as[NMAX];    // alphas of current layer (1 then 2)
__device__ float g_ad[NMAX];
__device__ float g_adB[NMAX];   // layer-3 ad
__device__ int   g_cnt[NMAX + 1];
__device__ int   g_ro[NMAX + 1];
__device__ int   g_nxt[NMAX];
__device__ int   g_csrc[EMAX];
__device__ int   g_bsum[64];
__device__ int   g_boff[64];
__device__ int   g_is64;
__device__ unsigned g_mx1, g_mx2, g_mx3;  // encoded global max of as per layer

__device__ __forceinline__ float lrelu(float x) { return x > 0.f ? x : NEG * x; }

// monotone float <-> uint encoding for atomicMax over signed floats
__device__ __forceinline__ unsigned fenc(float f) {
    unsigned u = __float_as_uint(f);
    return (u & 0x80000000u) ? ~u : (u | 0x80000000u);
}
__device__ __forceinline__ float fdec(unsigned u) {
    return (u & 0x80000000u) ? __uint_as_float(u & 0x7fffffffu) : __uint_as_float(~u);
}

__global__ void init_k() { g_mx1 = 0u; g_mx2 = 0u; g_mx3 = 0u; }

// ---------------- edge-index dtype detection ----------------
__global__ void detect_k(const void* ei) {
    int lane = threadIdx.x;
    const int* p = (const int*)ei;
    int v = p[2 * lane + 1];
    unsigned b = __ballot_sync(FULL, v == 0);
    if (lane == 0) g_is64 = (b == FULL) ? 1 : 0;
}

__device__ __forceinline__ int edge_val(const void* ei, int idx) {
    if (g_is64) return (int)((const long long*)ei)[idx];
    return ((const int*)ei)[idx];
}

// ---------------- CSR build ----------------
__global__ void zero_k(int n) {
    int i = blockIdx.x * blockDim.x + threadIdx.x;
    if (i < n) g_cnt[i] = 0;
}

__global__ void hist_k(const void* ei, int E) {
    int e = blockIdx.x * blockDim.x + threadIdx.x;
    if (e < E) {
        int d = edge_val(ei, E + e);
        atomicAdd(&g_cnt[d], 1);
    }
}

// multi-block exclusive scan of g_cnt[0..N) -> g_ro ; 1024 elems/block
__global__ __launch_bounds__(256) void scanA_k(int N) {
    __shared__ int wsum[8];
    int tid = threadIdx.x, lane = tid & 31, wid = tid >> 5;
    int base = blockIdx.x * 1024 + tid * 4;
    int v[4];
    #pragma unroll
    for (int k = 0; k < 4; k++) v[k] = (base + k < N) ? g_cnt[base + k] : 0;
    int s4 = v[0] + v[1] + v[2] + v[3];
    int x = s4;
    #pragma unroll
    for (int o = 1; o < 32; o <<= 1) {
        int t = __shfl_up_sync(FULL, x, o);
        if (lane >= o) x += t;
    }
    if (lane == 31) wsum[wid] = x;
    __syncthreads();
    if (wid == 0 && lane < 8) {
        int w = wsum[lane];
        #pragma unroll
        for (int o = 1; o < 8; o <<= 1) {
            int t = __shfl_up_sync(0xffu, w, o);
            if (lane >= o) w += t;
        }
        wsum[lane] = w;
    }
    __syncthreads();
    int excl = (wid ? wsum[wid - 1] : 0) + x - s4;
    int run = excl;
    #pragma unroll
    for (int k = 0; k < 4; k++) {
        if (base + k < N) g_ro[base + k] = run;
        run += v[k];
    }
    if (tid == 255) g_bsum[blockIdx.x] = wsum[7];
}

__global__ void scanB_k(int nb, int N) {
    int tid = threadIdx.x;  // 64 threads
    int lane = tid & 31, wid = tid >> 5;
    __shared__ int w0tot;
    int v = (tid < nb) ? g_bsum[tid] : 0;
    int x = v;
    #pragma unroll
    for (int o = 1; o < 32; o <<= 1) {
        int t = __shfl_up_sync(FULL, x, o);
        if (lane >= o) x += t;
    }
    if (wid == 0 && lane == 31) w0tot = x;
    __syncthreads();
    if (wid == 1) x += w0tot;
    g_boff[tid] = x - v;
    if (tid == 63) g_ro[N] = x;
}

__global__ __launch_bounds__(256) void scanC_k(int N) {
    int base = blockIdx.x * 1024 + threadIdx.x * 4;
    int off = g_boff[blockIdx.x];
    #pragma unroll
    for (int k = 0; k < 4; k++) {
        int i = base + k;
        if (i < N) {
            int r = g_ro[i] + off;
            g_ro[i] = r;
            g_nxt[i] = r;
        }
    }
}

__global__ void scat_k(const void* ei, int E) {
    int e = blockIdx.x * blockDim.x + threadIdx.x;
    if (e < E) {
        int s = edge_val(ei, e);
        int d = edge_val(ei, E + e);
        int p = atomicAdd(&g_nxt[d], 1);
        g_csrc[p] = s;
    }
}

// ---------------- GEMM layer 1: [N,256] x [256,48] -> g_h1 ; fused alpha + maxAS ----------------
__global__ __launch_bounds__(256) void gemm1_k(const float* __restrict__ X,
                                               const float* __restrict__ W,
                                               const float* __restrict__ av_s,
                                               const float* __restrict__ av_d, int N) {
    __shared__ float sX[64][68];
    __shared__ float sW[64][48];
    __shared__ float sWm[8];
    int tid = threadIdx.x;
    int tx = tid & 15, ty = tid >> 4;
    int lane = tid & 31, wid = tid >> 5;
    int row0 = blockIdx.x * 64;
    float acc[4][3];
    #pragma unroll
    for (int i = 0; i < 4; i++)
        #pragma unroll
        for (int j = 0; j < 3; j++) acc[i][j] = 0.f;

    for (int k0 = 0; k0 < 256; k0 += 64) {
        for (int i = tid; i < 64 * 16; i += 256) {
            int r = i >> 4; int kq = (i & 15) * 4;
            int gr = row0 + r;
            float4 v = (gr < N) ? *(const float4*)&X[(size_t)gr * 256 + k0 + kq]
                                : make_float4(0.f, 0.f, 0.f, 0.f);
            *(float4*)&sX[r][kq] = v;
        }
        for (int i = tid; i < 64 * 12; i += 256) {
            int r = i / 12; int cq = (i % 12) * 4;
            float4 v = *(const float4*)&W[(size_t)(k0 + r) * 48 + cq];
            *(float4*)&sW[r][cq] = v;
        }
        __syncthreads();
        #pragma unroll 16
        for (int k = 0; k < 64; k++) {
            float a0 = sX[ty * 4 + 0][k], a1 = sX[ty * 4 + 1][k];
            float a2 = sX[ty * 4 + 2][k], a3 = sX[ty * 4 + 3][k];
            float w0 = sW[k][tx * 3 + 0], w1 = sW[k][tx * 3 + 1], w2 = sW[k][tx * 3 + 2];
            acc[0][0] += a0 * w0; acc[0][1] += a0 * w1; acc[0][2] += a0 * w2;
            acc[1][0] += a1 * w0; acc[1][1] += a1 * w1; acc[1][2] += a1 * w2;
            acc[2][0] += a2 * w0; acc[2][1] += a2 * w1; acc[2][2] += a2 * w2;
            acc[3][0] += a3 * w0; acc[3][1] += a3 * w1; acc[3][2] += a3 * w2;
        }
        __syncthreads();
    }
    #pragma unroll
    for (int i = 0; i < 4; i++) {
        int gr = row0 + ty * 4 + i;
        if (gr < N) {
            #pragma unroll
            for (int j = 0; j < 3; j++)
                g_h1[(size_t)gr * 48 + tx * 3 + j] = acc[i][j];
        }
    }
    // fused alpha: reduce over 16 threads of the same row group
    float a_s[3], a_d[3];
    #pragma unroll
    for (int j = 0; j < 3; j++) { a_s[j] = av_s[tx * 3 + j]; a_d[j] = av_d[tx * 3 + j]; }
    float pmax = -INFINITY;
    #pragma unroll
    for (int i = 0; i < 4; i++) {
        float ps = acc[i][0] * a_s[0] + acc[i][1] * a_s[1] + acc[i][2] * a_s[2];
        float pd = acc[i][0] * a_d[0] + acc[i][1] * a_d[1] + acc[i][2] * a_d[2];
        #pragma unroll
        for (int o = 8; o; o >>= 1) {
            ps += __shfl_down_sync(FULL, ps, o, 16);
            pd += __shfl_down_sync(FULL, pd, o, 16);
        }
        if (tx == 0) {
            int gr = row0 + ty * 4 + i;
            if (gr < N) { g_as[gr] = ps; g_ad[gr] = pd; pmax = fmaxf(pmax, ps); }
        }
    }
    pmax = fmaxf(pmax, __shfl_xor_sync(FULL, pmax, 16));
    if (lane == 0) sWm[wid] = pmax;
    __syncthreads();
    if (wid == 0) {
        float v = (lane < 8) ? sWm[lane] : -INFINITY;
        #pragma unroll
        for (int o = 4; o; o >>= 1) v = fmaxf(v, __shfl_down_sync(FULL, v, o));
        if (lane == 0) atomicMax(&g_mx1, fenc(v));
    }
}

// ---------------- GEMM layer 2: g_out1 [N,48] x [48,60] -> g_h2h (fp16, padded 64) ----------------
__global__ __launch_bounds__(256) void gemm2_k(const float* __restrict__ W,
                                               const float* __restrict__ av_s,
                                               const float* __restrict__ av_d, int N) {
    __shared__ float sX[64][52];
    __shared__ float sW[48][64];
    __shared__ float sWm[8];
    int tid = threadIdx.x;
    int tx = tid & 15, ty = tid >> 4;
    int lane = tid & 31, wid = tid >> 5;
    int row0 = blockIdx.x * 64;

    for (int i = tid; i < 768; i += 256) {
        int r = i / 12; int kq = (i % 12) * 4;
        int gr = row0 + r;
        float4 v = (gr < N) ? *(const float4*)&g_out1[(size_t)gr * 48 + kq]
                            : make_float4(0.f, 0.f, 0.f, 0.f);
        *(float4*)&sX[r][kq] = v;
    }
    for (int i = tid; i < 720; i += 256) {
        int r = i / 15; int cq = (i % 15) * 4;
        float4 v = *(const float4*)&W[(size_t)r * 60 + cq];
        *(float4*)&sW[r][cq] = v;
    }
    __syncthreads();

    float acc[4][4];
    #pragma unroll
    for (int i = 0; i < 4; i++)
        #pragma unroll
        for (int j = 0; j < 4; j++) acc[i][j] = 0.f;

    #pragma unroll 12
    for (int k = 0; k < 48; k++) {
        float a0 = sX[ty * 4 + 0][k], a1 = sX[ty * 4 + 1][k];
        float a2 = sX[ty * 4 + 2][k], a3 = sX[ty * 4 + 3][k];
        float4 w = *(const float4*)&sW[k][tx * 4];
        acc[0][0] += a0 * w.x; acc[0][1] += a0 * w.y; acc[0][2] += a0 * w.z; acc[0][3] += a0 * w.w;
        acc[1][0] += a1 * w.x; acc[1][1] += a1 * w.y; acc[1][2] += a1 * w.z; acc[1][3] += a1 * w.w;
        acc[2][0] += a2 * w.x; acc[2][1] += a2 * w.y; acc[2][2] += a2 * w.z; acc[2][3] += a2 * w.w;
        acc[3][0] += a3 * w.x; acc[3][1] += a3 * w.y; acc[3][2] += a3 * w.z; acc[3][3] += a3 * w.w;
    }
    #pragma unroll
    for (int i = 0; i < 4; i++) {
        int gr = row0 + ty * 4 + i;
        if (gr < N) {
            int c0 = tx * 4;
            float v0 = (c0 + 0 < 60) ? acc[i][0] : 0.f;
            float v1 = (c0 + 1 < 60) ? acc[i][1] : 0.f;
            float v2 = (c0 + 2 < 60) ? acc[i][2] : 0.f;
            float v3 = (c0 + 3 < 60) ? acc[i][3] : 0.f;
            __half2 p01 = __floats2half2_rn(v0, v1);
            __half2 p23 = __floats2half2_rn(v2, v3);
            uint2 pk = make_uint2(*(unsigned*)&p01, *(unsigned*)&p23);
            *(uint2*)&g_h2h[(size_t)gr * 64 + c0] = pk;
        }
    }
    // fused alpha (cols >= 60 masked out; computed from fp32 accumulators)
    float a_s[4], a_d[4];
    #pragma unroll
    for (int j = 0; j < 4; j++) {
        int c = tx * 4 + j;
        a_s[j] = (c < 60) ? av_s[c] : 0.f;
        a_d[j] = (c < 60) ? av_d[c] : 0.f;
    }
    float pmax = -INFINITY;
    #pragma unroll
    for (int i = 0; i < 4; i++) {
        float ps = acc[i][0] * a_s[0] + acc[i][1] * a_s[1] + acc[i][2] * a_s[2] + acc[i][3] * a_s[3];
        float pd = acc[i][0] * a_d[0] + acc[i][1] * a_d[1] + acc[i][2] * a_d[2] + acc[i][3] * a_d[3];
        #pragma unroll
        for (int o = 8; o; o >>= 1) {
            ps += __shfl_down_sync(FULL, ps, o, 16);
            pd += __shfl_down_sync(FULL, pd, o, 16);
        }
        if (tx == 0) {
            int gr = row0 + ty * 4 + i;
            if (gr < N) { g_as[gr] = ps; g_ad[gr] = pd; pmax = fmaxf(pmax, ps); }
        }
    }
    pmax = fmaxf(pmax, __shfl_xor_sync(FULL, pmax, 16));
    if (lane == 0) sWm[wid] = pmax;
    __syncthreads();
    if (wid == 0) {
        float v = (lane < 8) ? sWm[lane] : -INFINITY;
        #pragma unroll
        for (int o = 4; o; o >>= 1) v = fmaxf(v, __shfl_down_sync(FULL, v, o));
        if (lane == 0) atomicMax(&g_mx2, fenc(v));
    }
}

// ---------------- fused segment softmax + aggregation (warp per node, single pass) ----------------
// Same warp structure as R5 (float4 acc, dual-half gather). LAYER==2 payload is fp16:
// each lane loads 8B (4 halfs) from the 128B-aligned row; logits/softmax stay fp32.
template <int LAYER>
__global__ __launch_bounds__(256) void agg_k(const float* __restrict__ bias,
                                             const float* __restrict__ W3,
                                             const float* __restrict__ as3,
                                             const float* __restrict__ ad3, int N) {
    constexpr int FV = (LAYER == 1) ? 12 : 16;   // active gather lanes per half-warp
    constexpr int FVO = (LAYER == 1) ? 12 : 15;  // lanes holding real output cols
    __shared__ float sWm[8];

    int tid = threadIdx.x;
    int n = (blockIdx.x * blockDim.x + tid) >> 5;
    int lane = tid & 31, wid = tid >> 5;
    bool valid = n < N;

    float maxAS = fdec((LAYER == 1) ? g_mx1 : g_mx2);
    int beg = 0, end = 0;
    float adn = 0.f, lself = 0.f, m = 0.f;
    if (valid) {
        beg = g_ro[n]; end = g_ro[n + 1];
        adn = g_ad[n];
        lself = lrelu(g_as[n] + adn);
        m = lrelu(maxAS + adn);
    }

    int half_id = lane >> 4;
    int hl = lane & 15;
    const bool act = hl < FV;
    float4 acc = make_float4(0.f, 0.f, 0.f, 0.f);
    float Sp = 0.f;
    for (int j0 = beg; j0 < end; j0 += 32) {
        int j = j0 + lane;
        int s = 0; float e = 0.f;
        if (j < end) {
            s = g_csrc[j];
            e = __expf(lrelu(g_as[s] + adn) - m);
            Sp += e;
        }
        int cnt = min(32, end - j0);
        for (int jj = 0; jj < cnt; jj += 2) {
            int idx = jj + half_id;
            float ee = __shfl_sync(FULL, e, idx);
            int ss = __shfl_sync(FULL, s, idx);
            if (act && idx < cnt) {
                if (LAYER == 1) {
                    float4 hv = *(const float4*)(g_h1 + (size_t)ss * 48 + hl * 4);
                    acc.x += ee * hv.x; acc.y += ee * hv.y;
                    acc.z += ee * hv.z; acc.w += ee * hv.w;
                } else {
                    uint2 raw = *(const uint2*)(g_h2h + (size_t)ss * 64 + hl * 4);
                    float2 f01 = __half22float2(*(__half2*)&raw.x);
                    float2 f23 = __half22float2(*(__half2*)&raw.y);
                    acc.x += ee * f01.x; acc.y += ee * f01.y;
                    acc.z += ee * f23.x; acc.w += ee * f23.y;
                }
            }
        }
    }
    // combine halves
    acc.x += __shfl_down_sync(FULL, acc.x, 16);
    acc.y += __shfl_down_sync(FULL, acc.y, 16);
    acc.z += __shfl_down_sync(FULL, acc.z, 16);
    acc.w += __shfl_down_sync(FULL, acc.w, 16);

    float es = __expf(lself - m);
    if (valid && lane < FV) {
        if (LAYER == 1) {
            float4 hv = *(const float4*)(g_h1 + (size_t)n * 48 + lane * 4);
            acc.x += es * hv.x; acc.y += es * hv.y;
            acc.z += es * hv.z; acc.w += es * hv.w;
        } else {
            uint2 raw = *(const uint2*)(g_h2h + (size_t)n * 64 + lane * 4);
            float2 f01 = __half22float2(*(__half2*)&raw.x);
            float2 f23 = __half22float2(*(__half2*)&raw.y);
            acc.x += es * f01.x; acc.y += es * f01.y;
            acc.z += es * f23.x; acc.w += es * f23.y;
        }
    }
    if (lane == 0) Sp += es;
    #pragma unroll
    for (int o = 16; o; o >>= 1) Sp += __shfl_xor_sync(FULL, Sp, o);

    float inv = 1.f / (Sp + 1e-16f);
    float4 o4 = make_float4(0.f, 0.f, 0.f, 0.f);
    if (lane < FVO) {
        float4 bb = *(const float4*)(bias + lane * 4);
        o4.x = fmaxf(acc.x * inv + bb.x, 0.f);
        o4.y = fmaxf(acc.y * inv + bb.y, 0.f);
        o4.z = fmaxf(acc.z * inv + bb.z, 0.f);
        o4.w = fmaxf(acc.w * inv + bb.w, 0.f);
        if (LAYER == 1 && valid) *(float4*)(g_out1 + (size_t)n * 48 + lane * 4) = o4;
    }
    if (LAYER == 2) {
        // fused layer-3 projection + alphas + maxAS3
        float d = 0.f;
        if (lane < FVO) {
            float4 w = *(const float4*)(W3 + lane * 4);
            d = o4.x * w.x + o4.y * w.y + o4.z * w.z + o4.w * w.w;
        }
        #pragma unroll
        for (int o = 16; o; o >>= 1) d += __shfl_xor_sync(FULL, d, o);
        float pm = -INFINITY;
        if (valid && lane == 0) {
            float a = d * as3[0];
            g_p3[n] = make_float2(a, d);
            g_adB[n] = d * ad3[0];
            pm = a;
        }
        if (lane == 0) sWm[wid] = pm;
        __syncthreads();
        if (wid == 0) {
            float v = (lane < 8) ? sWm[lane] : -INFINITY;
            #pragma unroll
            for (int o = 4; o; o >>= 1) v = fmaxf(v, __shfl_down_sync(FULL, v, o));
            if (lane == 0) atomicMax(&g_mx3, fenc(v));
        }
    }
}

// ---------------- layer 3 aggregation (scalar feature, single pass) ----------------
__global__ __launch_bounds__(256) void agg3_k(const float* __restrict__ b3,
                                              float* __restrict__ out, int N) {
    int n = (blockIdx.x * blockDim.x + threadIdx.x) >> 5;
    int lane = threadIdx.x & 31;
    if (n >= N) return;
    int beg = g_ro[n], end = g_ro[n + 1];
    float adn = g_adB[n];
    float2 pn = g_p3[n];
    float lself = lrelu(pn.x + adn);
    float m = lrelu(fdec(g_mx3) + adn);
    float S = 0.f, A = 0.f;
    for (int j = beg + lane; j < end; j += 32) {
        int s = g_csrc[j];
        float2 p = g_p3[s];
        float e = __expf(lrelu(p.x + adn) - m);
        S += e;
        A += e * p.y;
    }
    if (lane == 0) {
        float es = __expf(lself - m);
        S += es;
        A += es * pn.y;
    }
    #pragma unroll
    for (int o = 16; o; o >>= 1) {
        S += __shfl_xor_sync(FULL, S, o);
        A += __shfl_xor_sync(FULL, A, o);
    }
    if (lane == 0) out[n] = A / (S + 1e-16f) + b3[0];
}

// ---------------- launch ----------------
extern "C" void kernel_launch(void* const* d_in, const int* in_sizes, int n_in,
                              void* d_out, int out_size) {
    const float* x   = (const float*)d_in[0];
    const void*  ei  = d_in[1];
    // d_in[2] = edge_attr (ignored by the reference model)
    const float* W1  = (const float*)d_in[3];
    const float* as1 = (const float*)d_in[4];
    const float* ad1 = (const float*)d_in[5];
    const float* b1  = (const float*)d_in[6];
    const float* W2  = (const float*)d_in[7];
    const float* as2 = (const float*)d_in[8];
    const float* ad2 = (const float*)d_in[9];
    const float* b2  = (const float*)d_in[10];
    const float* W3  = (const float*)d_in[11];
    const float* as3 = (const float*)d_in[12];
    const float* ad3 = (const float*)d_in[13];
    const float* b3  = (const float*)d_in[14];

    int N = out_size;            // output is [N] floats
    int E = in_sizes[1] / 2;     // edge_index is [2, E]

    int blocksE = (E + 255) / 256;
    int wb = (N + 7) / 8;        // warp-per-node, 8 warps/block
    int gb = (N + 63) / 64;      // gemm row tiles
    int nb = (N + 1023) / 1024;  // scan blocks

    // one-time side-stream infrastructure (created on first, uncaptured, call)
    static cudaStream_t s2 = nullptr;
    static cudaEvent_t evFork = nullptr, evJoin = nullptr;
    if (s2 == nullptr) {
        cudaStreamCreateWithFlags(&s2, cudaStreamNonBlocking);
        cudaEventCreateWithFlags(&evFork, cudaEventDisableTiming);
        cudaEventCreateWithFlags(&evJoin, cudaEventDisableTiming);
    }

    init_k<<<1, 1>>>();

    // fork: CSR build on s2, GEMM1 on the main (captured) stream
    cudaEventRecord(evFork, 0);
    cudaStreamWaitEvent(s2, evFork, 0);

    zero_k<<<(N + 1023) / 1024, 1024, 0, s2>>>(N);
    detect_k<<<1, 32, 0, s2>>>(ei);
    hist_k<<<blocksE, 256, 0, s2>>>(ei, E);
    scanA_k<<<nb, 256, 0, s2>>>(N);
    scanB_k<<<1, 64, 0, s2>>>(nb, N);
    scanC_k<<<nb, 256, 0, s2>>>(N);
    scat_k<<<blocksE, 256, 0, s2>>>(ei, E);
    cudaEventRecord(evJoin, s2);

    gemm1_k<<<gb, 256>>>(x, W1, as1, ad1, N);

    // join: everything after needs both CSR and h1/alpha1
    cudaStreamWaitEvent(0, evJoin, 0);

    agg_k<1><<<wb, 256>>>(b1, nullptr, nullptr, nullptr, N);
    gemm2_k<<<gb, 256>>>(W2, as2, ad2, N);
    agg_k<2><<<wb, 256>>>(b2, W3, as3, ad3, N);
    agg3_k<<<wb, 256>>>(b3, (float*)d_out, N);
}

// round 12
// speedup vs baseline: 1.0801x; 1.0127x over previous
#include <cuda_runtime.h>
#include <cuda_fp16.h>
#include <cstdint>
#include <math.h>

#define NMAX 50176
#define EMAX 1700000
#define NEG 0.2f
#define FULL 0xffffffffu

// ---------------- device scratch (static; no allocation) ----------------
__device__ __half g_h1h[(size_t)NMAX * 48];  // fp16, 96B rows (sector-aligned)
__device__ float g_out1[(size_t)NMAX * 48];
__device__ __half g_h2h[(size_t)NMAX * 64];  // fp16, padded to 128B rows
__device__ float2 g_p3[NMAX];   // (as3*d, d) packed for layer-3 gather
__device__ float g_as[NMAX];    // alphas of current layer (1 then 2)
__device__ float g_ad[NMAX];
__device__ float g_adB[NMAX];   // layer-3 ad
__device__ int   g_cnt[NMAX + 1];
__device__ int   g_ro[NMAX + 1];
__device__ int   g_nxt[NMAX];
__device__ int   g_csrc[EMAX];
__device__ int   g_bsum[64];
__device__ int   g_boff[64];
__device__ int   g_is64;
__device__ unsigned g_mx1, g_mx2, g_mx3;  // encoded global max of as per layer

__device__ __forceinline__ float lrelu(float x) { return x > 0.f ? x : NEG * x; }

// monotone float <-> uint encoding for atomicMax over signed floats
__device__ __forceinline__ unsigned fenc(float f) {
    unsigned u = __float_as_uint(f);
    return (u & 0x80000000u) ? ~u : (u | 0x80000000u);
}
__device__ __forceinline__ float fdec(unsigned u) {
    return (u & 0x80000000u) ? __uint_as_float(u & 0x7fffffffu) : __uint_as_float(~u);
}

__global__ void init_k() { g_mx1 = 0u; g_mx2 = 0u; g_mx3 = 0u; }

// ---------------- edge-index dtype detection ----------------
__global__ void detect_k(const void* ei) {
    int lane = threadIdx.x;
    const int* p = (const int*)ei;
    int v = p[2 * lane + 1];
    unsigned b = __ballot_sync(FULL, v == 0);
    if (lane == 0) g_is64 = (b == FULL) ? 1 : 0;
}

__device__ __forceinline__ int edge_val(const void* ei, int idx) {
    if (g_is64) return (int)((const long long*)ei)[idx];
    return ((const int*)ei)[idx];
}

// ---------------- CSR build ----------------
__global__ void zero_k(int n) {
    int i = blockIdx.x * blockDim.x + threadIdx.x;
    if (i < n) g_cnt[i] = 0;
}

__global__ void hist_k(const void* ei, int E) {
    int e = blockIdx.x * blockDim.x + threadIdx.x;
    if (e < E) {
        int d = edge_val(ei, E + e);
        atomicAdd(&g_cnt[d], 1);
    }
}

// multi-block exclusive scan of g_cnt[0..N) -> g_ro ; 1024 elems/block
__global__ __launch_bounds__(256) void scanA_k(int N) {
    __shared__ int wsum[8];
    int tid = threadIdx.x, lane = tid & 31, wid = tid >> 5;
    int base = blockIdx.x * 1024 + tid * 4;
    int v[4];
    #pragma unroll
    for (int k = 0; k < 4; k++) v[k] = (base + k < N) ? g_cnt[base + k] : 0;
    int s4 = v[0] + v[1] + v[2] + v[3];
    int x = s4;
    #pragma unroll
    for (int o = 1; o < 32; o <<= 1) {
        int t = __shfl_up_sync(FULL, x, o);
        if (lane >= o) x += t;
    }
    if (lane == 31) wsum[wid] = x;
    __syncthreads();
    if (wid == 0 && lane < 8) {
        int w = wsum[lane];
        #pragma unroll
        for (int o = 1; o < 8; o <<= 1) {
            int t = __shfl_up_sync(0xffu, w, o);
            if (lane >= o) w += t;
        }
        wsum[lane] = w;
    }
    __syncthreads();
    int excl = (wid ? wsum[wid - 1] : 0) + x - s4;
    int run = excl;
    #pragma unroll
    for (int k = 0; k < 4; k++) {
        if (base + k < N) g_ro[base + k] = run;
        run += v[k];
    }
    if (tid == 255) g_bsum[blockIdx.x] = wsum[7];
}

__global__ void scanB_k(int nb, int N) {
    int tid = threadIdx.x;  // 64 threads
    int lane = tid & 31, wid = tid >> 5;
    __shared__ int w0tot;
    int v = (tid < nb) ? g_bsum[tid] : 0;
    int x = v;
    #pragma unroll
    for (int o = 1; o < 32; o <<= 1) {
        int t = __shfl_up_sync(FULL, x, o);
        if (lane >= o) x += t;
    }
    if (wid == 0 && lane == 31) w0tot = x;
    __syncthreads();
    if (wid == 1) x += w0tot;
    g_boff[tid] = x - v;
    if (tid == 63) g_ro[N] = x;
}

__global__ __launch_bounds__(256) void scanC_k(int N) {
    int base = blockIdx.x * 1024 + threadIdx.x * 4;
    int off = g_boff[blockIdx.x];
    #pragma unroll
    for (int k = 0; k < 4; k++) {
        int i = base + k;
        if (i < N) {
            int r = g_ro[i] + off;
            g_ro[i] = r;
            g_nxt[i] = r;
        }
    }
}

__global__ void scat_k(const void* ei, int E) {
    int e = blockIdx.x * blockDim.x + threadIdx.x;
    if (e < E) {
        int s = edge_val(ei, e);
        int d = edge_val(ei, E + e);
        int p = atomicAdd(&g_nxt[d], 1);
        g_csrc[p] = s;
    }
}

// ---------------- GEMM layer 1: [N,256] x [256,48] -> g_h1h (fp16, smem-staged) ----------------
__global__ __launch_bounds__(256) void gemm1_k(const float* __restrict__ X,
                                               const float* __restrict__ W,
                                               const float* __restrict__ av_s,
                                               const float* __restrict__ av_d, int N) {
    __shared__ float sX[64][68];
    __shared__ float sW[64][48];   // weights during mainloop; acc staging after
    __shared__ float sWm[8];
    int tid = threadIdx.x;
    int tx = tid & 15, ty = tid >> 4;
    int lane = tid & 31, wid = tid >> 5;
    int row0 = blockIdx.x * 64;
    float acc[4][3];
    #pragma unroll
    for (int i = 0; i < 4; i++)
        #pragma unroll
        for (int j = 0; j < 3; j++) acc[i][j] = 0.f;

    for (int k0 = 0; k0 < 256; k0 += 64) {
        for (int i = tid; i < 64 * 16; i += 256) {
            int r = i >> 4; int kq = (i & 15) * 4;
            int gr = row0 + r;
            float4 v = (gr < N) ? *(const float4*)&X[(size_t)gr * 256 + k0 + kq]
                                : make_float4(0.f, 0.f, 0.f, 0.f);
            *(float4*)&sX[r][kq] = v;
        }
        for (int i = tid; i < 64 * 12; i += 256) {
            int r = i / 12; int cq = (i % 12) * 4;
            float4 v = *(const float4*)&W[(size_t)(k0 + r) * 48 + cq];
            *(float4*)&sW[r][cq] = v;
        }
        __syncthreads();
        #pragma unroll 16
        for (int k = 0; k < 64; k++) {
            float a0 = sX[ty * 4 + 0][k], a1 = sX[ty * 4 + 1][k];
            float a2 = sX[ty * 4 + 2][k], a3 = sX[ty * 4 + 3][k];
            float w0 = sW[k][tx * 3 + 0], w1 = sW[k][tx * 3 + 1], w2 = sW[k][tx * 3 + 2];
            acc[0][0] += a0 * w0; acc[0][1] += a0 * w1; acc[0][2] += a0 * w2;
            acc[1][0] += a1 * w0; acc[1][1] += a1 * w1; acc[1][2] += a1 * w2;
            acc[2][0] += a2 * w0; acc[2][1] += a2 * w1; acc[2][2] += a2 * w2;
            acc[3][0] += a3 * w0; acc[3][1] += a3 * w1; acc[3][2] += a3 * w2;
        }
        __syncthreads();
    }
    // stage accumulators into sW (weights dead), then emit vectorized fp16 stores
    #pragma unroll
    for (int i = 0; i < 4; i++)
        #pragma unroll
        for (int j = 0; j < 3; j++)
            sW[ty * 4 + i][tx * 3 + j] = acc[i][j];
    __syncthreads();
    // 64 rows x 48 halfs = 768 uint2 (4 halfs each); 3 per thread, coalesced
    for (int p = tid; p < 768; p += 256) {
        int r = p / 12, c4 = (p % 12) * 4;
        int gr = row0 + r;
        if (gr < N) {
            float v0 = sW[r][c4 + 0], v1 = sW[r][c4 + 1];
            float v2 = sW[r][c4 + 2], v3 = sW[r][c4 + 3];
            __half2 p01 = __floats2half2_rn(v0, v1);
            __half2 p23 = __floats2half2_rn(v2, v3);
            uint2 pk = make_uint2(*(unsigned*)&p01, *(unsigned*)&p23);
            *(uint2*)&g_h1h[(size_t)gr * 48 + c4] = pk;
        }
    }
    // fused alpha from fp32 registers: reduce over 16 threads of the same row group
    float a_s[3], a_d[3];
    #pragma unroll
    for (int j = 0; j < 3; j++) { a_s[j] = av_s[tx * 3 + j]; a_d[j] = av_d[tx * 3 + j]; }
    float pmax = -INFINITY;
    #pragma unroll
    for (int i = 0; i < 4; i++) {
        float ps = acc[i][0] * a_s[0] + acc[i][1] * a_s[1] + acc[i][2] * a_s[2];
        float pd = acc[i][0] * a_d[0] + acc[i][1] * a_d[1] + acc[i][2] * a_d[2];
        #pragma unroll
        for (int o = 8; o; o >>= 1) {
            ps += __shfl_down_sync(FULL, ps, o, 16);
            pd += __shfl_down_sync(FULL, pd, o, 16);
        }
        if (tx == 0) {
            int gr = row0 + ty * 4 + i;
            if (gr < N) { g_as[gr] = ps; g_ad[gr] = pd; pmax = fmaxf(pmax, ps); }
        }
    }
    pmax = fmaxf(pmax, __shfl_xor_sync(FULL, pmax, 16));
    if (lane == 0) sWm[wid] = pmax;
    __syncthreads();
    if (wid == 0) {
        float v = (lane < 8) ? sWm[lane] : -INFINITY;
        #pragma unroll
        for (int o = 4; o; o >>= 1) v = fmaxf(v, __shfl_down_sync(FULL, v, o));
        if (lane == 0) atomicMax(&g_mx1, fenc(v));
    }
}

// ---------------- GEMM layer 2: g_out1 [N,48] x [48,60] -> g_h2h (fp16, padded 64) ----------------
__global__ __launch_bounds__(256) void gemm2_k(const float* __restrict__ W,
                                               const float* __restrict__ av_s,
                                               const float* __restrict__ av_d, int N) {
    __shared__ float sX[64][52];
    __shared__ float sW[48][64];
    __shared__ float sWm[8];
    int tid = threadIdx.x;
    int tx = tid & 15, ty = tid >> 4;
    int lane = tid & 31, wid = tid >> 5;
    int row0 = blockIdx.x * 64;

    for (int i = tid; i < 768; i += 256) {
        int r = i / 12; int kq = (i % 12) * 4;
        int gr = row0 + r;
        float4 v = (gr < N) ? *(const float4*)&g_out1[(size_t)gr * 48 + kq]
                            : make_float4(0.f, 0.f, 0.f, 0.f);
        *(float4*)&sX[r][kq] = v;
    }
    for (int i = tid; i < 720; i += 256) {
        int r = i / 15; int cq = (i % 15) * 4;
        float4 v = *(const float4*)&W[(size_t)r * 60 + cq];
        *(float4*)&sW[r][cq] = v;
    }
    __syncthreads();

    float acc[4][4];
    #pragma unroll
    for (int i = 0; i < 4; i++)
        #pragma unroll
        for (int j = 0; j < 4; j++) acc[i][j] = 0.f;

    #pragma unroll 12
    for (int k = 0; k < 48; k++) {
        float a0 = sX[ty * 4 + 0][k], a1 = sX[ty * 4 + 1][k];
        float a2 = sX[ty * 4 + 2][k], a3 = sX[ty * 4 + 3][k];
        float4 w = *(const float4*)&sW[k][tx * 4];
        acc[0][0] += a0 * w.x; acc[0][1] += a0 * w.y; acc[0][2] += a0 * w.z; acc[0][3] += a0 * w.w;
        acc[1][0] += a1 * w.x; acc[1][1] += a1 * w.y; acc[1][2] += a1 * w.z; acc[1][3] += a1 * w.w;
        acc[2][0] += a2 * w.x; acc[2][1] += a2 * w.y; acc[2][2] += a2 * w.z; acc[2][3] += a2 * w.w;
        acc[3][0] += a3 * w.x; acc[3][1] += a3 * w.y; acc[3][2] += a3 * w.z; acc[3][3] += a3 * w.w;
    }
    #pragma unroll
    for (int i = 0; i < 4; i++) {
        int gr = row0 + ty * 4 + i;
        if (gr < N) {
            int c0 = tx * 4;
            float v0 = (c0 + 0 < 60) ? acc[i][0] : 0.f;
            float v1 = (c0 + 1 < 60) ? acc[i][1] : 0.f;
            float v2 = (c0 + 2 < 60) ? acc[i][2] : 0.f;
            float v3 = (c0 + 3 < 60) ? acc[i][3] : 0.f;
            __half2 p01 = __floats2half2_rn(v0, v1);
            __half2 p23 = __floats2half2_rn(v2, v3);
            uint2 pk = make_uint2(*(unsigned*)&p01, *(unsigned*)&p23);
            *(uint2*)&g_h2h[(size_t)gr * 64 + c0] = pk;
        }
    }
    // fused alpha (cols >= 60 masked out; computed from fp32 accumulators)
    float a_s[4], a_d[4];
    #pragma unroll
    for (int j = 0; j < 4; j++) {
        int c = tx * 4 + j;
        a_s[j] = (c < 60) ? av_s[c] : 0.f;
        a_d[j] = (c < 60) ? av_d[c] : 0.f;
    }
    float pmax = -INFINITY;
    #pragma unroll
    for (int i = 0; i < 4; i++) {
        float ps = acc[i][0] * a_s[0] + acc[i][1] * a_s[1] + acc[i][2] * a_s[2] + acc[i][3] * a_s[3];
        float pd = acc[i][0] * a_d[0] + acc[i][1] * a_d[1] + acc[i][2] * a_d[2] + acc[i][3] * a_d[3];
        #pragma unroll
        for (int o = 8; o; o >>= 1) {
            ps += __shfl_down_sync(FULL, ps, o, 16);
            pd += __shfl_down_sync(FULL, pd, o, 16);
        }
        if (tx == 0) {
            int gr = row0 + ty * 4 + i;
            if (gr < N) { g_as[gr] = ps; g_ad[gr] = pd; pmax = fmaxf(pmax, ps); }
        }
    }
    pmax = fmaxf(pmax, __shfl_xor_sync(FULL, pmax, 16));
    if (lane == 0) sWm[wid] = pmax;
    __syncthreads();
    if (wid == 0) {
        float v = (lane < 8) ? sWm[lane] : -INFINITY;
        #pragma unroll
        for (int o = 4; o; o >>= 1) v = fmaxf(v, __shfl_down_sync(FULL, v, o));
        if (lane == 0) atomicMax(&g_mx2, fenc(v));
    }
}

// ---------------- fused segment softmax + aggregation (warp per node, single pass) ----------------
// Both layers gather fp16 payload (uint2 = 4 halfs per lane); softmax/accum fp32.
// LAYER==1: rows of 48 halfs (96B, sector-aligned); LAYER==2: rows of 64 halfs (128B).
template <int LAYER>
__global__ __launch_bounds__(256) void agg_k(const float* __restrict__ bias,
                                             const float* __restrict__ W3,
                                             const float* __restrict__ as3,
                                             const float* __restrict__ ad3, int N) {
    constexpr int ST = (LAYER == 1) ? 48 : 64;   // row stride in halfs
    constexpr int FV = ST / 4;                   // active gather lanes (12 or 16)
    constexpr int FVO = (LAYER == 1) ? 12 : 15;  // lanes holding real output cols
    const __half* h = (LAYER == 1) ? g_h1h : g_h2h;
    __shared__ float sWm[8];

    int tid = threadIdx.x;
    int n = (blockIdx.x * blockDim.x + tid) >> 5;
    int lane = tid & 31, wid = tid >> 5;
    bool valid = n < N;

    float maxAS = fdec((LAYER == 1) ? g_mx1 : g_mx2);
    int beg = 0, end = 0;
    float adn = 0.f, lself = 0.f, m = 0.f;
    if (valid) {
        beg = g_ro[n]; end = g_ro[n + 1];
        adn = g_ad[n];
        lself = lrelu(g_as[n] + adn);
        m = lrelu(maxAS + adn);
    }

    int half_id = lane >> 4;
    int hl = lane & 15;
    const bool act = hl < FV;
    float4 acc = make_float4(0.f, 0.f, 0.f, 0.f);
    float Sp = 0.f;
    for (int j0 = beg; j0 < end; j0 += 32) {
        int j = j0 + lane;
        int s = 0; float e = 0.f;
        if (j < end) {
            s = g_csrc[j];
            e = __expf(lrelu(g_as[s] + adn) - m);
            Sp += e;
        }
        int cnt = min(32, end - j0);
        for (int jj = 0; jj < cnt; jj += 2) {
            int idx = jj + half_id;
            float ee = __shfl_sync(FULL, e, idx);
            int ss = __shfl_sync(FULL, s, idx);
            if (act && idx < cnt) {
                uint2 raw = *(const uint2*)(h + (size_t)ss * ST + hl * 4);
                float2 f01 = __half22float2(*(__half2*)&raw.x);
                float2 f23 = __half22float2(*(__half2*)&raw.y);
                acc.x += ee * f01.x; acc.y += ee * f01.y;
                acc.z += ee * f23.x; acc.w += ee * f23.y;
            }
        }
    }
    // combine halves
    acc.x += __shfl_down_sync(FULL, acc.x, 16);
    acc.y += __shfl_down_sync(FULL, acc.y, 16);
    acc.z += __shfl_down_sync(FULL, acc.z, 16);
    acc.w += __shfl_down_sync(FULL, acc.w, 16);

    float es = __expf(lself - m);
    if (valid && lane < FV) {
        uint2 raw = *(const uint2*)(h + (size_t)n * ST + lane * 4);
        float2 f01 = __half22float2(*(__half2*)&raw.x);
        float2 f23 = __half22float2(*(__half2*)&raw.y);
        acc.x += es * f01.x; acc.y += es * f01.y;
        acc.z += es * f23.x; acc.w += es * f23.y;
    }
    if (lane == 0) Sp += es;
    #pragma unroll
    for (int o = 16; o; o >>= 1) Sp += __shfl_xor_sync(FULL, Sp, o);

    float inv = 1.f / (Sp + 1e-16f);
    float4 o4 = make_float4(0.f, 0.f, 0.f, 0.f);
    if (lane < FVO) {
        float4 bb = *(const float4*)(bias + lane * 4);
        o4.x = fmaxf(acc.x * inv + bb.x, 0.f);
        o4.y = fmaxf(acc.y * inv + bb.y, 0.f);
        o4.z = fmaxf(acc.z * inv + bb.z, 0.f);
        o4.w = fmaxf(acc.w * inv + bb.w, 0.f);
        if (LAYER == 1 && valid) *(float4*)(g_out1 + (size_t)n * 48 + lane * 4) = o4;
    }
    if (LAYER == 2) {
        // fused layer-3 projection + alphas + maxAS3
        float d = 0.f;
        if (lane < FVO) {
            float4 w = *(const float4*)(W3 + lane * 4);
            d = o4.x * w.x + o4.y * w.y + o4.z * w.z + o4.w * w.w;
        }
        #pragma unroll
        for (int o = 16; o; o >>= 1) d += __shfl_xor_sync(FULL, d, o);
        float pm = -INFINITY;
        if (valid && lane == 0) {
            float a = d * as3[0];
            g_p3[n] = make_float2(a, d);
            g_adB[n] = d * ad3[0];
            pm = a;
        }
        if (lane == 0) sWm[wid] = pm;
        __syncthreads();
        if (wid == 0) {
            float v = (lane < 8) ? sWm[lane] : -INFINITY;
            #pragma unroll
            for (int o = 4; o; o >>= 1) v = fmaxf(v, __shfl_down_sync(FULL, v, o));
            if (lane == 0) atomicMax(&g_mx3, fenc(v));
        }
    }
}

// ---------------- layer 3 aggregation (scalar feature, single pass) ----------------
__global__ __launch_bounds__(256) void agg3_k(const float* __restrict__ b3,
                                              float* __restrict__ out, int N) {
    int n = (blockIdx.x * blockDim.x + threadIdx.x) >> 5;
    int lane = threadIdx.x & 31;
    if (n >= N) return;
    int beg = g_ro[n], end = g_ro[n + 1];
    float adn = g_adB[n];
    float2 pn = g_p3[n];
    float lself = lrelu(pn.x + adn);
    float m = lrelu(fdec(g_mx3) + adn);
    float S = 0.f, A = 0.f;
    for (int j = beg + lane; j < end; j += 32) {
        int s = g_csrc[j];
        float2 p = g_p3[s];
        float e = __expf(lrelu(p.x + adn) - m);
        S += e;
        A += e * p.y;
    }
    if (lane == 0) {
        float es = __expf(lself - m);
        S += es;
        A += es * pn.y;
    }
    #pragma unroll
    for (int o = 16; o; o >>= 1) {
        S += __shfl_xor_sync(FULL, S, o);
        A += __shfl_xor_sync(FULL, A, o);
    }
    if (lane == 0) out[n] = A / (S + 1e-16f) + b3[0];
}

// ---------------- launch ----------------
extern "C" void kernel_launch(void* const* d_in, const int* in_sizes, int n_in,
                              void* d_out, int out_size) {
    const float* x   = (const float*)d_in[0];
    const void*  ei  = d_in[1];
    // d_in[2] = edge_attr (ignored by the reference model)
    const float* W1  = (const float*)d_in[3];
    const float* as1 = (const float*)d_in[4];
    const float* ad1 = (const float*)d_in[5];
    const float* b1  = (const float*)d_in[6];
    const float* W2  = (const float*)d_in[7];
    const float* as2 = (const float*)d_in[8];
    const float* ad2 = (const float*)d_in[9];
    const float* b2  = (const float*)d_in[10];
    const float* W3  = (const float*)d_in[11];
    const float* as3 = (const float*)d_in[12];
    const float* ad3 = (const float*)d_in[13];
    const float* b3  = (const float*)d_in[14];

    int N = out_size;            // output is [N] floats
    int E = in_sizes[1] / 2;     // edge_index is [2, E]

    int blocksE = (E + 255) / 256;
    int wb = (N + 7) / 8;        // warp-per-node, 8 warps/block
    int gb = (N + 63) / 64;      // gemm row tiles
    int nb = (N + 1023) / 1024;  // scan blocks

    // one-time side-stream infrastructure (created on first, uncaptured, call)
    static cudaStream_t s2 = nullptr;
    static cudaEvent_t evFork = nullptr, evJoin = nullptr;
    if (s2 == nullptr) {
        cudaStreamCreateWithFlags(&s2, cudaStreamNonBlocking);
        cudaEventCreateWithFlags(&evFork, cudaEventDisableTiming);
        cudaEventCreateWithFlags(&evJoin, cudaEventDisableTiming);
    }

    init_k<<<1, 1>>>();

    // fork: CSR build on s2, GEMM1 on the main (captured) stream
    cudaEventRecord(evFork, 0);
    cudaStreamWaitEvent(s2, evFork, 0);

    zero_k<<<(N + 1023) / 1024, 1024, 0, s2>>>(N);
    detect_k<<<1, 32, 0, s2>>>(ei);
    hist_k<<<blocksE, 256, 0, s2>>>(ei, E);
    scanA_k<<<nb, 256, 0, s2>>>(N);
    scanB_k<<<1, 64, 0, s2>>>(nb, N);
    scanC_k<<<nb, 256, 0, s2>>>(N);
    scat_k<<<blocksE, 256, 0, s2>>>(ei, E);
    cudaEventRecord(evJoin, s2);

    gemm1_k<<<gb, 256>>>(x, W1, as1, ad1, N);

    // join: everything after needs both CSR and h1/alpha1
    cudaStreamWaitEvent(0, evJoin, 0);

    agg_k<1><<<wb, 256>>>(b1, nullptr, nullptr, nullptr, N);
    gemm2_k<<<gb, 256>>>(W2, as2, ad2, N);
    agg_k<2><<<wb, 256>>>(b2, W3, as3, ad3, N);
    agg3_k<<<wb, 256>>>(b3, (float*)d_out, N);
}

// round 13
// speedup vs baseline: 1.1146x; 1.0320x over previous
#include <cuda_runtime.h>
#include <cuda_fp16.h>
#include <cstdint>
#include <math.h>

#define NMAX 50176
#define EMAX 1700000
#define NEG 0.2f
#define FULL 0xffffffffu

// ---------------- device scratch (static; no allocation) ----------------
__device__ __half g_h1h[(size_t)NMAX * 48];  // fp16, 96B rows (sector-aligned)
__device__ float g_out1[(size_t)NMAX * 48];
__device__ __half g_h2h[(size_t)NMAX * 64];  // fp16, padded to 128B rows
__device__ float2 g_p3[NMAX];   // (as3*d, d) packed for layer-3 gather
__device__ float g_as[NMAX];    // alphas of current layer (1 then 2)
__device__ float g_ad[NMAX];
__device__ float g_adB[NMAX];   // layer-3 ad
__device__ int   g_cnt[NMAX + 1];
__device__ int   g_ro[NMAX + 1];
__device__ int   g_nxt[NMAX];
__device__ int   g_csrc[EMAX];
__device__ int   g_bsum[64];
__device__ int   g_boff[64];
__device__ int   g_is64;
__device__ unsigned g_mx1, g_mx2, g_mx3;  // encoded global max of as per layer

__device__ __forceinline__ float lrelu(float x) { return x > 0.f ? x : NEG * x; }

// monotone float <-> uint encoding for atomicMax over signed floats
__device__ __forceinline__ unsigned fenc(float f) {
    unsigned u = __float_as_uint(f);
    return (u & 0x80000000u) ? ~u : (u | 0x80000000u);
}
__device__ __forceinline__ float fdec(unsigned u) {
    return (u & 0x80000000u) ? __uint_as_float(u & 0x7fffffffu) : __uint_as_float(~u);
}

__global__ void init_k() { g_mx1 = 0u; g_mx2 = 0u; g_mx3 = 0u; }

// ---------------- edge-index dtype detection ----------------
__global__ void detect_k(const void* ei) {
    int lane = threadIdx.x;
    const int* p = (const int*)ei;
    int v = p[2 * lane + 1];
    unsigned b = __ballot_sync(FULL, v == 0);
    if (lane == 0) g_is64 = (b == FULL) ? 1 : 0;
}

__device__ __forceinline__ int edge_val(const void* ei, int idx) {
    if (g_is64) return (int)((const long long*)ei)[idx];
    return ((const int*)ei)[idx];
}

// ---------------- CSR build ----------------
__global__ void zero_k(int n) {
    int i = blockIdx.x * blockDim.x + threadIdx.x;
    if (i < n) g_cnt[i] = 0;
}

__global__ void hist_k(const void* ei, int E) {
    int e = blockIdx.x * blockDim.x + threadIdx.x;
    if (e < E) {
        int d = edge_val(ei, E + e);
        atomicAdd(&g_cnt[d], 1);
    }
}

// multi-block exclusive scan of g_cnt[0..N) -> g_ro ; 1024 elems/block
__global__ __launch_bounds__(256) void scanA_k(int N) {
    __shared__ int wsum[8];
    int tid = threadIdx.x, lane = tid & 31, wid = tid >> 5;
    int base = blockIdx.x * 1024 + tid * 4;
    int v[4];
    #pragma unroll
    for (int k = 0; k < 4; k++) v[k] = (base + k < N) ? g_cnt[base + k] : 0;
    int s4 = v[0] + v[1] + v[2] + v[3];
    int x = s4;
    #pragma unroll
    for (int o = 1; o < 32; o <<= 1) {
        int t = __shfl_up_sync(FULL, x, o);
        if (lane >= o) x += t;
    }
    if (lane == 31) wsum[wid] = x;
    __syncthreads();
    if (wid == 0 && lane < 8) {
        int w = wsum[lane];
        #pragma unroll
        for (int o = 1; o < 8; o <<= 1) {
            int t = __shfl_up_sync(0xffu, w, o);
            if (lane >= o) w += t;
        }
        wsum[lane] = w;
    }
    __syncthreads();
    int excl = (wid ? wsum[wid - 1] : 0) + x - s4;
    int run = excl;
    #pragma unroll
    for (int k = 0; k < 4; k++) {
        if (base + k < N) g_ro[base + k] = run;
        run += v[k];
    }
    if (tid == 255) g_bsum[blockIdx.x] = wsum[7];
}

__global__ void scanB_k(int nb, int N) {
    int tid = threadIdx.x;  // 64 threads
    int lane = tid & 31, wid = tid >> 5;
    __shared__ int w0tot;
    int v = (tid < nb) ? g_bsum[tid] : 0;
    int x = v;
    #pragma unroll
    for (int o = 1; o < 32; o <<= 1) {
        int t = __shfl_up_sync(FULL, x, o);
        if (lane >= o) x += t;
    }
    if (wid == 0 && lane == 31) w0tot = x;
    __syncthreads();
    if (wid == 1) x += w0tot;
    g_boff[tid] = x - v;
    if (tid == 63) g_ro[N] = x;
}

__global__ __launch_bounds__(256) void scanC_k(int N) {
    int base = blockIdx.x * 1024 + threadIdx.x * 4;
    int off = g_boff[blockIdx.x];
    #pragma unroll
    for (int k = 0; k < 4; k++) {
        int i = base + k;
        if (i < N) {
            int r = g_ro[i] + off;
            g_ro[i] = r;
            g_nxt[i] = r;
        }
    }
}

__global__ void scat_k(const void* ei, int E) {
    int e = blockIdx.x * blockDim.x + threadIdx.x;
    if (e < E) {
        int s = edge_val(ei, e);
        int d = edge_val(ei, E + e);
        int p = atomicAdd(&g_nxt[d], 1);
        g_csrc[p] = s;
    }
}

// ---------------- GEMM layer 1: [N,256] x [256,48] -> g_h1h (fp16, smem-staged) ----------------
__global__ __launch_bounds__(256) void gemm1_k(const float* __restrict__ X,
                                               const float* __restrict__ W,
                                               const float* __restrict__ av_s,
                                               const float* __restrict__ av_d, int N) {
    __shared__ float sX[64][68];
    __shared__ float sW[64][48];   // weights during mainloop; acc staging after
    __shared__ float sWm[8];
    int tid = threadIdx.x;
    int tx = tid & 15, ty = tid >> 4;
    int lane = tid & 31, wid = tid >> 5;
    int row0 = blockIdx.x * 64;
    float acc[4][3];
    #pragma unroll
    for (int i = 0; i < 4; i++)
        #pragma unroll
        for (int j = 0; j < 3; j++) acc[i][j] = 0.f;

    for (int k0 = 0; k0 < 256; k0 += 64) {
        for (int i = tid; i < 64 * 16; i += 256) {
            int r = i >> 4; int kq = (i & 15) * 4;
            int gr = row0 + r;
            float4 v = (gr < N) ? *(const float4*)&X[(size_t)gr * 256 + k0 + kq]
                                : make_float4(0.f, 0.f, 0.f, 0.f);
            *(float4*)&sX[r][kq] = v;
        }
        for (int i = tid; i < 64 * 12; i += 256) {
            int r = i / 12; int cq = (i % 12) * 4;
            float4 v = *(const float4*)&W[(size_t)(k0 + r) * 48 + cq];
            *(float4*)&sW[r][cq] = v;
        }
        __syncthreads();
        #pragma unroll 16
        for (int k = 0; k < 64; k++) {
            float a0 = sX[ty * 4 + 0][k], a1 = sX[ty * 4 + 1][k];
            float a2 = sX[ty * 4 + 2][k], a3 = sX[ty * 4 + 3][k];
            float w0 = sW[k][tx * 3 + 0], w1 = sW[k][tx * 3 + 1], w2 = sW[k][tx * 3 + 2];
            acc[0][0] += a0 * w0; acc[0][1] += a0 * w1; acc[0][2] += a0 * w2;
            acc[1][0] += a1 * w0; acc[1][1] += a1 * w1; acc[1][2] += a1 * w2;
            acc[2][0] += a2 * w0; acc[2][1] += a2 * w1; acc[2][2] += a2 * w2;
            acc[3][0] += a3 * w0; acc[3][1] += a3 * w1; acc[3][2] += a3 * w2;
        }
        __syncthreads();
    }
    // stage accumulators into sW (weights dead), then emit vectorized fp16 stores
    #pragma unroll
    for (int i = 0; i < 4; i++)
        #pragma unroll
        for (int j = 0; j < 3; j++)
            sW[ty * 4 + i][tx * 3 + j] = acc[i][j];
    __syncthreads();
    // 64 rows x 48 halfs = 768 uint2 (4 halfs each); 3 per thread, coalesced
    for (int p = tid; p < 768; p += 256) {
        int r = p / 12, c4 = (p % 12) * 4;
        int gr = row0 + r;
        if (gr < N) {
            float v0 = sW[r][c4 + 0], v1 = sW[r][c4 + 1];
            float v2 = sW[r][c4 + 2], v3 = sW[r][c4 + 3];
            __half2 p01 = __floats2half2_rn(v0, v1);
            __half2 p23 = __floats2half2_rn(v2, v3);
            uint2 pk = make_uint2(*(unsigned*)&p01, *(unsigned*)&p23);
            *(uint2*)&g_h1h[(size_t)gr * 48 + c4] = pk;
        }
    }
    // fused alpha from fp32 registers: reduce over 16 threads of the same row group
    float a_s[3], a_d[3];
    #pragma unroll
    for (int j = 0; j < 3; j++) { a_s[j] = av_s[tx * 3 + j]; a_d[j] = av_d[tx * 3 + j]; }
    float pmax = -INFINITY;
    #pragma unroll
    for (int i = 0; i < 4; i++) {
        float ps = acc[i][0] * a_s[0] + acc[i][1] * a_s[1] + acc[i][2] * a_s[2];
        float pd = acc[i][0] * a_d[0] + acc[i][1] * a_d[1] + acc[i][2] * a_d[2];
        #pragma unroll
        for (int o = 8; o; o >>= 1) {
            ps += __shfl_down_sync(FULL, ps, o, 16);
            pd += __shfl_down_sync(FULL, pd, o, 16);
        }
        if (tx == 0) {
            int gr = row0 + ty * 4 + i;
            if (gr < N) { g_as[gr] = ps; g_ad[gr] = pd; pmax = fmaxf(pmax, ps); }
        }
    }
    pmax = fmaxf(pmax, __shfl_xor_sync(FULL, pmax, 16));
    if (lane == 0) sWm[wid] = pmax;
    __syncthreads();
    if (wid == 0) {
        float v = (lane < 8) ? sWm[lane] : -INFINITY;
        #pragma unroll
        for (int o = 4; o; o >>= 1) v = fmaxf(v, __shfl_down_sync(FULL, v, o));
        if (lane == 0) atomicMax(&g_mx1, fenc(v));
    }
}

// ---------------- GEMM layer 2: g_out1 [N,48] x [48,60] -> g_h2h (fp16, padded 64) ----------------
__global__ __launch_bounds__(256) void gemm2_k(const float* __restrict__ W,
                                               const float* __restrict__ av_s,
                                               const float* __restrict__ av_d, int N) {
    __shared__ float sX[64][52];
    __shared__ float sW[48][64];
    __shared__ float sWm[8];
    int tid = threadIdx.x;
    int tx = tid & 15, ty = tid >> 4;
    int lane = tid & 31, wid = tid >> 5;
    int row0 = blockIdx.x * 64;

    for (int i = tid; i < 768; i += 256) {
        int r = i / 12; int kq = (i % 12) * 4;
        int gr = row0 + r;
        float4 v = (gr < N) ? *(const float4*)&g_out1[(size_t)gr * 48 + kq]
                            : make_float4(0.f, 0.f, 0.f, 0.f);
        *(float4*)&sX[r][kq] = v;
    }
    for (int i = tid; i < 720; i += 256) {
        int r = i / 15; int cq = (i % 15) * 4;
        float4 v = *(const float4*)&W[(size_t)r * 60 + cq];
        *(float4*)&sW[r][cq] = v;
    }
    __syncthreads();

    float acc[4][4];
    #pragma unroll
    for (int i = 0; i < 4; i++)
        #pragma unroll
        for (int j = 0; j < 4; j++) acc[i][j] = 0.f;

    #pragma unroll 12
    for (int k = 0; k < 48; k++) {
        float a0 = sX[ty * 4 + 0][k], a1 = sX[ty * 4 + 1][k];
        float a2 = sX[ty * 4 + 2][k], a3 = sX[ty * 4 + 3][k];
        float4 w = *(const float4*)&sW[k][tx * 4];
        acc[0][0] += a0 * w.x; acc[0][1] += a0 * w.y; acc[0][2] += a0 * w.z; acc[0][3] += a0 * w.w;
        acc[1][0] += a1 * w.x; acc[1][1] += a1 * w.y; acc[1][2] += a1 * w.z; acc[1][3] += a1 * w.w;
        acc[2][0] += a2 * w.x; acc[2][1] += a2 * w.y; acc[2][2] += a2 * w.z; acc[2][3] += a2 * w.w;
        acc[3][0] += a3 * w.x; acc[3][1] += a3 * w.y; acc[3][2] += a3 * w.z; acc[3][3] += a3 * w.w;
    }
    #pragma unroll
    for (int i = 0; i < 4; i++) {
        int gr = row0 + ty * 4 + i;
        if (gr < N) {
            int c0 = tx * 4;
            float v0 = (c0 + 0 < 60) ? acc[i][0] : 0.f;
            float v1 = (c0 + 1 < 60) ? acc[i][1] : 0.f;
            float v2 = (c0 + 2 < 60) ? acc[i][2] : 0.f;
            float v3 = (c0 + 3 < 60) ? acc[i][3] : 0.f;
            __half2 p01 = __floats2half2_rn(v0, v1);
            __half2 p23 = __floats2half2_rn(v2, v3);
            uint2 pk = make_uint2(*(unsigned*)&p01, *(unsigned*)&p23);
            *(uint2*)&g_h2h[(size_t)gr * 64 + c0] = pk;
        }
    }
    // fused alpha (cols >= 60 masked out; computed from fp32 accumulators)
    float a_s[4], a_d[4];
    #pragma unroll
    for (int j = 0; j < 4; j++) {
        int c = tx * 4 + j;
        a_s[j] = (c < 60) ? av_s[c] : 0.f;
        a_d[j] = (c < 60) ? av_d[c] : 0.f;
    }
    float pmax = -INFINITY;
    #pragma unroll
    for (int i = 0; i < 4; i++) {
        float ps = acc[i][0] * a_s[0] + acc[i][1] * a_s[1] + acc[i][2] * a_s[2] + acc[i][3] * a_s[3];
        float pd = acc[i][0] * a_d[0] + acc[i][1] * a_d[1] + acc[i][2] * a_d[2] + acc[i][3] * a_d[3];
        #pragma unroll
        for (int o = 8; o; o >>= 1) {
            ps += __shfl_down_sync(FULL, ps, o, 16);
            pd += __shfl_down_sync(FULL, pd, o, 16);
        }
        if (tx == 0) {
            int gr = row0 + ty * 4 + i;
            if (gr < N) { g_as[gr] = ps; g_ad[gr] = pd; pmax = fmaxf(pmax, ps); }
        }
    }
    pmax = fmaxf(pmax, __shfl_xor_sync(FULL, pmax, 16));
    if (lane == 0) sWm[wid] = pmax;
    __syncthreads();
    if (wid == 0) {
        float v = (lane < 8) ? sWm[lane] : -INFINITY;
        #pragma unroll
        for (int o = 4; o; o >>= 1) v = fmaxf(v, __shfl_down_sync(FULL, v, o));
        if (lane == 0) atomicMax(&g_mx2, fenc(v));
    }
}

// ---------------- fused segment softmax + aggregation (warp per node, single pass) ----------------
// fp16 payload gather (uint2 = 4 halfs per lane); softmax/accum fp32.
// Inner loop is 2-edge unrolled per half-warp: both gathers issue before any
// dependent FMA (MLP=2), with separate accumulator sets to break FMA chains.
template <int LAYER>
__global__ __launch_bounds__(256) void agg_k(const float* __restrict__ bias,
                                             const float* __restrict__ W3,
                                             const float* __restrict__ as3,
                                             const float* __restrict__ ad3, int N) {
    constexpr int ST = (LAYER == 1) ? 48 : 64;   // row stride in halfs
    constexpr int FV = ST / 4;                   // active gather lanes (12 or 16)
    constexpr int FVO = (LAYER == 1) ? 12 : 15;  // lanes holding real output cols
    const __half* h = (LAYER == 1) ? g_h1h : g_h2h;
    __shared__ float sWm[8];

    int tid = threadIdx.x;
    int n = (blockIdx.x * blockDim.x + tid) >> 5;
    int lane = tid & 31, wid = tid >> 5;
    bool valid = n < N;

    float maxAS = fdec((LAYER == 1) ? g_mx1 : g_mx2);
    int beg = 0, end = 0;
    float adn = 0.f, lself = 0.f, m = 0.f;
    if (valid) {
        beg = g_ro[n]; end = g_ro[n + 1];
        adn = g_ad[n];
        lself = lrelu(g_as[n] + adn);
        m = lrelu(maxAS + adn);
    }

    int half_id = lane >> 4;
    int hl = lane & 15;
    const bool act = hl < FV;
    float4 accA = make_float4(0.f, 0.f, 0.f, 0.f);
    float4 accB = make_float4(0.f, 0.f, 0.f, 0.f);
    float Sp = 0.f;
    for (int j0 = beg; j0 < end; j0 += 32) {
        int j = j0 + lane;
        int s = 0; float e = 0.f;
        if (j < end) {
            s = g_csrc[j];
            e = __expf(lrelu(g_as[s] + adn) - m);
            Sp += e;
        }
        int cnt = min(32, end - j0);
        int jj = 0;
        for (; jj + 4 <= cnt; jj += 4) {
            int i0 = jj + half_id, i1 = jj + 2 + half_id;
            float e0 = __shfl_sync(FULL, e, i0);
            int s0 = __shfl_sync(FULL, s, i0);
            float e1 = __shfl_sync(FULL, e, i1);
            int s1 = __shfl_sync(FULL, s, i1);
            if (act) {
                uint2 r0 = *(const uint2*)(h + (size_t)s0 * ST + hl * 4);
                uint2 r1 = *(const uint2*)(h + (size_t)s1 * ST + hl * 4);
                float2 a01 = __half22float2(*(__half2*)&r0.x);
                float2 a23 = __half22float2(*(__half2*)&r0.y);
                float2 b01 = __half22float2(*(__half2*)&r1.x);
                float2 b23 = __half22float2(*(__half2*)&r1.y);
                accA.x += e0 * a01.x; accA.y += e0 * a01.y;
                accA.z += e0 * a23.x; accA.w += e0 * a23.y;
                accB.x += e1 * b01.x; accB.y += e1 * b01.y;
                accB.z += e1 * b23.x; accB.w += e1 * b23.y;
            }
        }
        for (; jj < cnt; jj += 2) {
            int idx = jj + half_id;
            float ee = __shfl_sync(FULL, e, idx);
            int ss = __shfl_sync(FULL, s, idx);
            if (act && idx < cnt) {
                uint2 raw = *(const uint2*)(h + (size_t)ss * ST + hl * 4);
                float2 f01 = __half22float2(*(__half2*)&raw.x);
                float2 f23 = __half22float2(*(__half2*)&raw.y);
                accA.x += ee * f01.x; accA.y += ee * f01.y;
                accA.z += ee * f23.x; accA.w += ee * f23.y;
            }
        }
    }
    float4 acc = make_float4(accA.x + accB.x, accA.y + accB.y,
                             accA.z + accB.z, accA.w + accB.w);
    // combine halves
    acc.x += __shfl_down_sync(FULL, acc.x, 16);
    acc.y += __shfl_down_sync(FULL, acc.y, 16);
    acc.z += __shfl_down_sync(FULL, acc.z, 16);
    acc.w += __shfl_down_sync(FULL, acc.w, 16);

    float es = __expf(lself - m);
    if (valid && lane < FV) {
        uint2 raw = *(const uint2*)(h + (size_t)n * ST + lane * 4);
        float2 f01 = __half22float2(*(__half2*)&raw.x);
        float2 f23 = __half22float2(*(__half2*)&raw.y);
        acc.x += es * f01.x; acc.y += es * f01.y;
        acc.z += es * f23.x; acc.w += es * f23.y;
    }
    if (lane == 0) Sp += es;
    #pragma unroll
    for (int o = 16; o; o >>= 1) Sp += __shfl_xor_sync(FULL, Sp, o);

    float inv = 1.f / (Sp + 1e-16f);
    float4 o4 = make_float4(0.f, 0.f, 0.f, 0.f);
    if (lane < FVO) {
        float4 bb = *(const float4*)(bias + lane * 4);
        o4.x = fmaxf(acc.x * inv + bb.x, 0.f);
        o4.y = fmaxf(acc.y * inv + bb.y, 0.f);
        o4.z = fmaxf(acc.z * inv + bb.z, 0.f);
        o4.w = fmaxf(acc.w * inv + bb.w, 0.f);
        if (LAYER == 1 && valid) *(float4*)(g_out1 + (size_t)n * 48 + lane * 4) = o4;
    }
    if (LAYER == 2) {
        // fused layer-3 projection + alphas + maxAS3
        float d = 0.f;
        if (lane < FVO) {
            float4 w = *(const float4*)(W3 + lane * 4);
            d = o4.x * w.x + o4.y * w.y + o4.z * w.z + o4.w * w.w;
        }
        #pragma unroll
        for (int o = 16; o; o >>= 1) d += __shfl_xor_sync(FULL, d, o);
        float pm = -INFINITY;
        if (valid && lane == 0) {
            float a = d * as3[0];
            g_p3[n] = make_float2(a, d);
            g_adB[n] = d * ad3[0];
            pm = a;
        }
        if (lane == 0) sWm[wid] = pm;
        __syncthreads();
        if (wid == 0) {
            float v = (lane < 8) ? sWm[lane] : -INFINITY;
            #pragma unroll
            for (int o = 4; o; o >>= 1) v = fmaxf(v, __shfl_down_sync(FULL, v, o));
            if (lane == 0) atomicMax(&g_mx3, fenc(v));
        }
    }
}

// ---------------- layer 3 aggregation (scalar feature, single pass) ----------------
__global__ __launch_bounds__(256) void agg3_k(const float* __restrict__ b3,
                                              float* __restrict__ out, int N) {
    int n = (blockIdx.x * blockDim.x + threadIdx.x) >> 5;
    int lane = threadIdx.x & 31;
    if (n >= N) return;
    int beg = g_ro[n], end = g_ro[n + 1];
    float adn = g_adB[n];
    float2 pn = g_p3[n];
    float lself = lrelu(pn.x + adn);
    float m = lrelu(fdec(g_mx3) + adn);
    float S = 0.f, A = 0.f;
    for (int j = beg + lane; j < end; j += 32) {
        int s = g_csrc[j];
        float2 p = g_p3[s];
        float e = __expf(lrelu(p.x + adn) - m);
        S += e;
        A += e * p.y;
    }
    if (lane == 0) {
        float es = __expf(lself - m);
        S += es;
        A += es * pn.y;
    }
    #pragma unroll
    for (int o = 16; o; o >>= 1) {
        S += __shfl_xor_sync(FULL, S, o);
        A += __shfl_xor_sync(FULL, A, o);
    }
    if (lane == 0) out[n] = A / (S + 1e-16f) + b3[0];
}

// ---------------- launch ----------------
extern "C" void kernel_launch(void* const* d_in, const int* in_sizes, int n_in,
                              void* d_out, int out_size) {
    const float* x   = (const float*)d_in[0];
    const void*  ei  = d_in[1];
    // d_in[2] = edge_attr (ignored by the reference model)
    const float* W1  = (const float*)d_in[3];
    const float* as1 = (const float*)d_in[4];
    const float* ad1 = (const float*)d_in[5];
    const float* b1  = (const float*)d_in[6];
    const float* W2  = (const float*)d_in[7];
    const float* as2 = (const float*)d_in[8];
    const float* ad2 = (const float*)d_in[9];
    const float* b2  = (const float*)d_in[10];
    const float* W3  = (const float*)d_in[11];
    const float* as3 = (const float*)d_in[12];
    const float* ad3 = (const float*)d_in[13];
    const float* b3  = (const float*)d_in[14];

    int N = out_size;            // output is [N] floats
    int E = in_sizes[1] / 2;     // edge_index is [2, E]

    int blocksE = (E + 255) / 256;
    int wb = (N + 7) / 8;        // warp-per-node, 8 warps/block
    int gb = (N + 63) / 64;      // gemm row tiles
    int nb = (N + 1023) / 1024;  // scan blocks

    // one-time side-stream infrastructure (created on first, uncaptured, call)
    static cudaStream_t s2 = nullptr;
    static cudaEvent_t evFork = nullptr, evJoin = nullptr;
    if (s2 == nullptr) {
        cudaStreamCreateWithFlags(&s2, cudaStreamNonBlocking);
        cudaEventCreateWithFlags(&evFork, cudaEventDisableTiming);
        cudaEventCreateWithFlags(&evJoin, cudaEventDisableTiming);
    }

    init_k<<<1, 1>>>();

    // fork: CSR build on s2, GEMM1 on the main (captured) stream
    cudaEventRecord(evFork, 0);
    cudaStreamWaitEvent(s2, evFork, 0);

    zero_k<<<(N + 1023) / 1024, 1024, 0, s2>>>(N);
    detect_k<<<1, 32, 0, s2>>>(ei);
    hist_k<<<blocksE, 256, 0, s2>>>(ei, E);
    scanA_k<<<nb, 256, 0, s2>>>(N);
    scanB_k<<<1, 64, 0, s2>>>(nb, N);
    scanC_k<<<nb, 256, 0, s2>>>(N);
    scat_k<<<blocksE, 256, 0, s2>>>(ei, E);
    cudaEventRecord(evJoin, s2);

    gemm1_k<<<gb, 256>>>(x, W1, as1, ad1, N);

    // join: everything after needs both CSR and h1/alpha1
    cudaStreamWaitEvent(0, evJoin, 0);

    agg_k<1><<<wb, 256>>>(b1, nullptr, nullptr, nullptr, N);
    gemm2_k<<<gb, 256>>>(W2, as2, ad2, N);
    agg_k<2><<<wb, 256>>>(b2, W3, as3, ad3, N);
    agg3_k<<<wb, 256>>>(b3, (float*)d_out, N);
}